// round 13
// baseline (speedup 1.0000x reference)
#include <cuda_runtime.h>
#include <cuda_fp16.h>
#include <math.h>
#include <stdint.h>

// Problem constants
#define Dm    1024
#define DQv   256
#define DHv   512
#define Pp    6
#define BATCH 8
#define Tt    2048
#define BT    (BATCH*Tt)       // 16384
#define NHEAD 8                // sign, aux, 6 digit heads
#define HBW   (NHEAD*DHv)      // 4096

// ------------------- scratch (static device globals; no cudaMalloc) -------
__device__ float  g_ctx[(size_t)BT * Dm];        // 64 MiB  (pre-LN fp32 context)
__device__ __half g_ctxh[(size_t)BT * Dm];       // 32 MiB  (post-LN fp16 context)
__device__ __half g_hidh[(size_t)BT * Dm];       // 32 MiB  (fp16 hidden)
__device__ __half g_hbig[(size_t)BT * HBW];      // 128 MiB (pre-LN head hidden, fp16)
__device__ float  g_opc[9 * Dm];
__device__ float  g_ptc[10 * Dm];
__device__ float  g_posc[Pp * DHv];
__device__ __half g_wctx_th[(size_t)Dm * Dm];    // ctx_w[0:1024,:]^T [N,K] fp16
__device__ __half g_whead_th[(size_t)NHEAD * DHv * Dm]; // W1' [512,1024] fp16

__device__ __forceinline__ float gelu_exact(float x) {
    return 0.5f * x * (1.0f + erff(x * 0.70710678118654752f));
}
__device__ __forceinline__ uint32_t smem_u32(const void* p) {
    uint32_t a;
    asm("{ .reg .u64 t; cvta.to.shared.u64 t, %1; cvt.u32.u64 %0, t; }" : "=r"(a) : "l"(p));
    return a;
}
__device__ __forceinline__ void cp16(uint32_t dst, const void* src) {
    asm volatile("cp.async.cg.shared.global [%0], [%1], 16;" :: "r"(dst), "l"(src));
}
#define CP_COMMIT() asm volatile("cp.async.commit_group;" ::: "memory")
#define CP_WAIT1()  asm volatile("cp.async.wait_group 1;" ::: "memory")
#define CP_WAIT0()  asm volatile("cp.async.wait_group 0;" ::: "memory")

__device__ __forceinline__ void mma_f16(float* c, const uint32_t* a, const uint32_t* b) {
    asm volatile("mma.sync.aligned.m16n8k16.row.col.f32.f16.f16.f32 "
        "{%0,%1,%2,%3}, {%4,%5,%6,%7}, {%8,%9}, {%0,%1,%2,%3};"
        : "+f"(c[0]), "+f"(c[1]), "+f"(c[2]), "+f"(c[3])
        : "r"(a[0]), "r"(a[1]), "r"(a[2]), "r"(a[3]), "r"(b[0]), "r"(b[1]));
}
__device__ __forceinline__ void ldm_x4(uint32_t& r0, uint32_t& r1, uint32_t& r2,
                                       uint32_t& r3, uint32_t addr) {
    asm volatile("ldmatrix.sync.aligned.m8n8.x4.shared.b16 {%0,%1,%2,%3}, [%4];"
        : "=r"(r0), "=r"(r1), "=r"(r2), "=r"(r3) : "r"(addr));
}

// ------------------- precompute embedding contributions -------------------
__global__ void precompute_kernel(const float* __restrict__ op_embed,
                                  const float* __restrict__ pt_embed,
                                  const float* __restrict__ pos_embed,
                                  const float* __restrict__ ctx_w,
                                  const float* __restrict__ dig_w1) {
    int idx = blockIdx.x * blockDim.x + threadIdx.x;
    if (idx < 9 * Dm) {
        int i = idx >> 10, n = idx & (Dm - 1);
        float s = 0.f;
        #pragma unroll 4
        for (int q = 0; q < DQv; q++)
            s += op_embed[i * DQv + q] * ctx_w[(size_t)(Dm + q) * Dm + n];
        g_opc[idx] = s;
    } else if (idx < 19 * Dm) {
        int j = idx - 9 * Dm;
        int i = j >> 10, n = j & (Dm - 1);
        float s = 0.f;
        #pragma unroll 4
        for (int q = 0; q < DQv; q++)
            s += pt_embed[i * DQv + q] * ctx_w[(size_t)(Dm + DQv + q) * Dm + n];
        g_ptc[j] = s;
    } else if (idx < 19 * Dm + Pp * DHv) {
        int j = idx - 19 * Dm;
        int p = j >> 9, h = j & (DHv - 1);
        float s = 0.f;
        #pragma unroll 4
        for (int q = 0; q < DQv; q++)
            s += pos_embed[p * DQv + q] * dig_w1[(size_t)p * 1280 * DHv + (size_t)(Dm + q) * DHv + h];
        g_posc[j] = s;
    }
}

// ------------------- round hidden to fp16 ---------------------------------
__global__ __launch_bounds__(256) void round_hidden(const float* __restrict__ hidden) {
    size_t i = (size_t)(blockIdx.x * 256 + threadIdx.x) * 4;
    float4 v = *(const float4*)(hidden + i);
    __half2* dst = (__half2*)(g_hidh + i);
    dst[0] = __floats2half2_rn(v.x, v.y);
    dst[1] = __floats2half2_rn(v.z, v.w);
}

// ------------------- weight transpose: [K=1024, N] -> [N, K] fp16 ---------
__global__ __launch_bounds__(256) void transpose_w(const float* __restrict__ ctx_w,
                                                   const float* __restrict__ sign_w1,
                                                   const float* __restrict__ aux_w1,
                                                   const float* __restrict__ dig_w1) {
    __shared__ float tbuf[32][33];
    int mat = blockIdx.z;
    const float* src; __half* dst; int ncols;
    if (mat == 0)      { src = ctx_w;   dst = g_wctx_th;                     ncols = Dm; }
    else if (mat == 1) { src = sign_w1; dst = g_whead_th;                    ncols = DHv; }
    else if (mat == 2) { src = aux_w1;  dst = g_whead_th + (size_t)DHv * Dm; ncols = DHv; }
    else {
        int p = mat - 3;
        src = dig_w1 + (size_t)p * 1280 * DHv;
        dst = g_whead_th + (size_t)(2 + p) * DHv * Dm;
        ncols = DHv;
    }
    int n0 = blockIdx.x * 32;
    int k0 = blockIdx.y * 32;
    if (n0 >= ncols) return;
    #pragma unroll
    for (int j = 0; j < 4; j++)
        tbuf[threadIdx.y + j * 8][threadIdx.x] =
            src[(size_t)(k0 + threadIdx.y + j * 8) * ncols + n0 + threadIdx.x];
    __syncthreads();
    #pragma unroll
    for (int j = 0; j < 4; j++) {
        float v = tbuf[threadIdx.x][threadIdx.y + j * 8];
        dst[(size_t)(n0 + threadIdx.y + j * 8) * Dm + k0 + threadIdx.x] = __float2half_rn(v);
    }
}

// ------------------- fp16 mma.sync GEMM, K-tile 64, 2-stage cp.async ------
// 128x128 block, 4 warps, 64x64/warp.  Fragment double-buffering across k16.
#define NKT 16
#define LDHB 144                       // bytes per smem row (64 halves + 16B pad)
#define ATILE_B (128 * LDHB)           // 18432 B per operand per stage
#define STAGE_B (2 * ATILE_B)          // 36864 B

// load all fragments for k16 sub-step `sidx` (kbase = sidx*32 bytes)
#define LOAD_FRAGS(sidx, bf, af) do {                                                   \
    int _kb = (sidx) * 32;                                                              \
    _Pragma("unroll")                                                                   \
    for (int _p = 0; _p < 4; _p++) {                                                    \
        int _in0 = 2 * _p;                                                              \
        uint32_t _ad = Bb + (uint32_t)((wn + (_in0 + (lm >> 1)) * 8 + li) * LDHB        \
                                       + _kb + (lm & 1) * 16);                          \
        ldm_x4((bf)[_in0][0], (bf)[_in0][1], (bf)[_in0 + 1][0], (bf)[_in0 + 1][1], _ad);\
    }                                                                                   \
    _Pragma("unroll")                                                                   \
    for (int _im = 0; _im < 4; _im++) {                                                 \
        int _rb = wm + _im * 16;                                                        \
        uint32_t _ad = Ab + (uint32_t)((_rb + (lm & 1) * 8 + li) * LDHB                 \
                                       + _kb + (lm >> 1) * 16);                         \
        ldm_x4((af)[_im][0], (af)[_im][1], (af)[_im][2], (af)[_im][3], _ad);            \
    }                                                                                   \
} while (0)

#define DO_MMAS(bf, af) do {                                                            \
    _Pragma("unroll")                                                                   \
    for (int _im = 0; _im < 4; _im++)                                                   \
        _Pragma("unroll")                                                               \
        for (int _in = 0; _in < 8; _in++)                                               \
            mma_f16(acc[_im][_in], (af)[_im], (bf)[_in]);                               \
} while (0)

__global__ __launch_bounds__(128, 2) void mma_gemm(int mode,
                                                   const int* __restrict__ op_t,
                                                   const int* __restrict__ pt_t,
                                                   const float* __restrict__ ctx_b,
                                                   const float* __restrict__ sign_b1,
                                                   const float* __restrict__ aux_b1,
                                                   const float* __restrict__ dig_b1) {
    extern __shared__ char smem[];
    uint32_t sbase = smem_u32(smem);

    int tid = threadIdx.x;
    int wid = tid >> 5, lane = tid & 31;
    int grp = lane >> 2, thr = lane & 3;
    int li = lane & 7, lm = lane >> 3;   // ldmatrix row index / matrix index
    int wm = (wid >> 1) * 64, wn = (wid & 1) * 64;
    int bn = blockIdx.x * 128, bm = blockIdx.y * 128, z = blockIdx.z;

    const __half* Aptr = (mode == 0 ? g_hidh : g_ctxh) + (size_t)bm * Dm;
    const __half* Bptr = (mode == 0 ? g_wctx_th : g_whead_th + (size_t)z * DHv * Dm)
                         + (size_t)bn * Dm;

    float acc[4][8][4];
    #pragma unroll
    for (int a = 0; a < 4; a++)
        #pragma unroll
        for (int b = 0; b < 8; b++)
            #pragma unroll
            for (int c = 0; c < 4; c++) acc[a][b][c] = 0.f;

    // preload stage 0 (64-wide K tile: 128 rows x 8 chunks of 16B per operand)
    {
        uint32_t sA = sbase, sB = sbase + ATILE_B;
        #pragma unroll
        for (int j = 0; j < 8; j++) {
            int idx = tid + j * 128;
            int r = idx >> 3, c = idx & 7;
            cp16(sA + (uint32_t)(r * LDHB + c * 16), Aptr + (size_t)r * Dm + c * 8);
            cp16(sB + (uint32_t)(r * LDHB + c * 16), Bptr + (size_t)r * Dm + c * 8);
        }
        CP_COMMIT();
    }

    for (int kt = 0; kt < NKT; kt++) {
        int buf = kt & 1;
        if (kt + 1 < NKT) {
            int k0 = (kt + 1) * 64;
            uint32_t sA = sbase + (uint32_t)(buf ^ 1) * STAGE_B;
            uint32_t sB = sA + ATILE_B;
            #pragma unroll
            for (int j = 0; j < 8; j++) {
                int idx = tid + j * 128;
                int r = idx >> 3, c = idx & 7;
                cp16(sA + (uint32_t)(r * LDHB + c * 16), Aptr + (size_t)r * Dm + k0 + c * 8);
                cp16(sB + (uint32_t)(r * LDHB + c * 16), Bptr + (size_t)r * Dm + k0 + c * 8);
            }
            CP_COMMIT();
            CP_WAIT1();
        } else {
            CP_WAIT0();
        }
        __syncthreads();

        uint32_t Ab = sbase + (uint32_t)buf * STAGE_B;
        uint32_t Bb = Ab + ATILE_B;

        // fragment double-buffer across the four k16 sub-steps
        uint32_t bf0[8][2], bf1[8][2], af0[4][4], af1[4][4];
        LOAD_FRAGS(0, bf0, af0);
        LOAD_FRAGS(1, bf1, af1);      // cover step-0 MMAs too
        DO_MMAS(bf0, af0);            // s = 0
        LOAD_FRAGS(2, bf0, af0);
        DO_MMAS(bf1, af1);            // s = 1
        LOAD_FRAGS(3, bf1, af1);
        DO_MMAS(bf0, af0);            // s = 2
        DO_MMAS(bf1, af1);            // s = 3

        __syncthreads();
    }

    // ---- epilogue ----
    const float* b1 = nullptr; const float* posc = nullptr;
    if (mode == 1) {
        if (z == 0)      b1 = sign_b1;
        else if (z == 1) b1 = aux_b1;
        else { b1 = dig_b1 + (z - 2) * DHv; posc = g_posc + (z - 2) * DHv; }
    }
    #pragma unroll
    for (int im = 0; im < 4; im++) {
        #pragma unroll
        for (int half = 0; half < 2; half++) {
            int row = bm + wm + im * 16 + grp + half * 8;
            if (mode == 0) {
                int op = op_t[row >> 11];
                int pt = pt_t[row];
                const float* ocp = g_opc + op * Dm + bn;
                const float* pcp = g_ptc + pt * Dm + bn;
                const float* bpv = ctx_b + bn;
                float* dst = g_ctx + (size_t)row * Dm + bn;
                #pragma unroll
                for (int in = 0; in < 8; in++) {
                    int cl = wn + in * 8 + 2 * thr;
                    float2 v;
                    v.x = acc[im][in][half * 2 + 0] + ocp[cl]     + pcp[cl]     + bpv[cl];
                    v.y = acc[im][in][half * 2 + 1] + ocp[cl + 1] + pcp[cl + 1] + bpv[cl + 1];
                    *(float2*)(dst + cl) = v;
                }
            } else {
                __half* dst = g_hbig + (size_t)row * HBW + z * DHv + bn;
                #pragma unroll
                for (int in = 0; in < 8; in++) {
                    int cl = wn + in * 8 + 2 * thr;
                    int col = bn + cl;
                    float vx = acc[im][in][half * 2 + 0] + b1[col];
                    float vy = acc[im][in][half * 2 + 1] + b1[col + 1];
                    if (posc) { vx += posc[col]; vy += posc[col + 1]; }
                    *(__half2*)(dst + cl) = __floats2half2_rn(vx, vy);
                }
            }
        }
    }
}

// ------------------- LN(1024) + GELU : g_ctx (fp32) -> g_ctxh (fp16) ------
__global__ __launch_bounds__(256) void ln_gelu_ctx(const float* __restrict__ g,
                                                   const float* __restrict__ beta) {
    int row = blockIdx.x;
    int tid = threadIdx.x;
    int lane = tid & 31, wid = tid >> 5;
    const float* base = g_ctx + (size_t)row * Dm;
    float4 v = *(const float4*)&base[tid * 4];
    float s  = v.x + v.y + v.z + v.w;
    float ss = v.x * v.x + v.y * v.y + v.z * v.z + v.w * v.w;
    #pragma unroll
    for (int off = 16; off; off >>= 1) {
        s  += __shfl_xor_sync(0xffffffffu, s, off);
        ss += __shfl_xor_sync(0xffffffffu, ss, off);
    }
    __shared__ float sh_s[8], sh_ss[8];
    if (lane == 0) { sh_s[wid] = s; sh_ss[wid] = ss; }
    __syncthreads();
    if (tid == 0) {
        float a = 0.f, b2 = 0.f;
        #pragma unroll
        for (int i = 0; i < 8; i++) { a += sh_s[i]; b2 += sh_ss[i]; }
        sh_s[0] = a; sh_ss[0] = b2;
    }
    __syncthreads();
    float mean = sh_s[0] * (1.f / Dm);
    float var  = sh_ss[0] * (1.f / Dm) - mean * mean;
    float rstd = rsqrtf(var + 1e-5f);
    int c = tid * 4;
    float o0 = gelu_exact((v.x - mean) * rstd * g[c + 0] + beta[c + 0]);
    float o1 = gelu_exact((v.y - mean) * rstd * g[c + 1] + beta[c + 1]);
    float o2 = gelu_exact((v.z - mean) * rstd * g[c + 2] + beta[c + 2]);
    float o3 = gelu_exact((v.w - mean) * rstd * g[c + 3] + beta[c + 3]);
    __half2* dst = (__half2*)(g_ctxh + (size_t)row * Dm + c);
    dst[0] = __floats2half2_rn(o0, o1);
    dst[1] = __floats2half2_rn(o2, o3);
}

// ------------------- final: LN(512)+GELU + tiny GEMM (512 -> oc), fused ---
__global__ __launch_bounds__(256) void head_final(const float* __restrict__ sign_g,
                                                  const float* __restrict__ sign_beta,
                                                  const float* __restrict__ sign_w2,
                                                  const float* __restrict__ sign_b2,
                                                  const float* __restrict__ dig_g,
                                                  const float* __restrict__ dig_beta,
                                                  const float* __restrict__ dig_w2,
                                                  const float* __restrict__ dig_b2,
                                                  const float* __restrict__ aux_w2,
                                                  const float* __restrict__ aux_b2,
                                                  float* __restrict__ out) {
    int head = blockIdx.y;
    int oc; bool ln;
    const float *g = nullptr, *bt = nullptr, *w2, *b2;
    if (head == 0)      { oc = 3;  ln = true;  g = sign_g; bt = sign_beta; w2 = sign_w2; b2 = sign_b2; }
    else if (head == 1) { oc = 1;  ln = false; w2 = aux_w2; b2 = aux_b2; }
    else {
        int p = head - 2;
        oc = 10; ln = true;
        g = dig_g + p * DHv; bt = dig_beta + p * DHv;
        w2 = dig_w2 + (size_t)p * DHv * 10; b2 = dig_b2 + p * 10;
    }

    __shared__ float w2s[10 * DHv];
    for (int i = threadIdx.x; i < DHv * oc; i += 256) {
        int k = i / oc, o = i - k * oc;
        w2s[o * DHv + k] = w2[i];
    }
    __syncthreads();

    int wid = threadIdx.x >> 5, lane = threadIdx.x & 31;
    int row = blockIdx.x * 8 + wid;
    const __half* hb = g_hbig + (size_t)row * HBW + head * DHv;

    float v[16];
    #pragma unroll
    for (int j = 0; j < 16; j++)
        v[j] = __half2float(hb[lane + 32 * j]);

    float mean = 0.f, rstd = 1.f;
    if (ln) {
        float s = 0.f, ss = 0.f;
        #pragma unroll
        for (int j = 0; j < 16; j++) { s += v[j]; ss += v[j] * v[j]; }
        #pragma unroll
        for (int off = 16; off; off >>= 1) {
            s  += __shfl_xor_sync(0xffffffffu, s, off);
            ss += __shfl_xor_sync(0xffffffffu, ss, off);
        }
        mean = s * (1.f / DHv);
        float var = ss * (1.f / DHv) - mean * mean;
        rstd = rsqrtf(var + 1e-5f);
    }

    float psum[10];
    #pragma unroll
    for (int o = 0; o < 10; o++) psum[o] = 0.f;

    #pragma unroll
    for (int j = 0; j < 16; j++) {
        int k = lane + 32 * j;
        float x = v[j];
        if (ln) x = (x - mean) * rstd * g[k] + bt[k];
        x = gelu_exact(x);
        #pragma unroll
        for (int o = 0; o < 10; o++)
            if (o < oc) psum[o] = fmaf(x, w2s[o * DHv + k], psum[o]);
    }
    #pragma unroll
    for (int o = 0; o < 10; o++)
        if (o < oc)
            #pragma unroll
            for (int off = 16; off; off >>= 1)
                psum[o] += __shfl_xor_sync(0xffffffffu, psum[o], off);

    if (lane == 0) {
        if (head == 0) {
            for (int o = 0; o < 3; o++) out[(size_t)row * 3 + o] = psum[o] + b2[o];
        } else if (head == 1) {
            out[(size_t)BT * 63 + row] = psum[0] + b2[0];
        } else {
            int p = head - 2;
            for (int o = 0; o < 10; o++)
                out[(size_t)BT * 3 + (size_t)row * 60 + p * 10 + o] = psum[o] + b2[o];
        }
    }
}

// ------------------- launch ------------------------------------------------
extern "C" void kernel_launch(void* const* d_in, const int* in_sizes, int n_in,
                              void* d_out, int out_size) {
    const float* hidden    = (const float*)d_in[0];
    const int*   op_t      = (const int*)  d_in[1];
    const int*   pt_t      = (const int*)  d_in[2];
    const float* op_embed  = (const float*)d_in[3];
    const float* pt_embed  = (const float*)d_in[4];
    const float* pos_embed = (const float*)d_in[5];
    const float* ctx_w     = (const float*)d_in[6];
    const float* ctx_b     = (const float*)d_in[7];
    const float* ctx_g     = (const float*)d_in[8];
    const float* ctx_beta  = (const float*)d_in[9];
    const float* sign_w1   = (const float*)d_in[10];
    const float* sign_b1   = (const float*)d_in[11];
    const float* sign_g    = (const float*)d_in[12];
    const float* sign_beta = (const float*)d_in[13];
    const float* sign_w2   = (const float*)d_in[14];
    const float* sign_b2   = (const float*)d_in[15];
    const float* dig_w1    = (const float*)d_in[16];
    const float* dig_b1    = (const float*)d_in[17];
    const float* dig_g     = (const float*)d_in[18];
    const float* dig_beta  = (const float*)d_in[19];
    const float* dig_w2    = (const float*)d_in[20];
    const float* dig_b2    = (const float*)d_in[21];
    const float* aux_w1    = (const float*)d_in[22];
    const float* aux_b1    = (const float*)d_in[23];
    const float* aux_w2    = (const float*)d_in[24];
    const float* aux_b2    = (const float*)d_in[25];
    float* out = (float*)d_out;

    const int SMEM_REQ = 2 * STAGE_B;   // 73728 B
    static int attr_set = 0;
    if (!attr_set) {
        cudaFuncSetAttribute(mma_gemm, cudaFuncAttributeMaxDynamicSharedMemorySize, SMEM_REQ);
        attr_set = 1;
    }

    // 1. embedding-contribution precompute (tiny)
    precompute_kernel<<<(19 * Dm + Pp * DHv + 255) / 256, 256>>>(
        op_embed, pt_embed, pos_embed, ctx_w, dig_w1);

    // 2. weight transpose -> K-major fp16 + round hidden to fp16
    transpose_w<<<dim3(32, 32, 9), dim3(32, 8)>>>(ctx_w, sign_w1, aux_w1, dig_w1);
    round_hidden<<<(BT * Dm / 4) / 256, 256>>>(hidden);

    // 3. context GEMM (pre-LN): [16384,1024] x [1024,1024]  (fp16 mma.sync)
    mma_gemm<<<dim3(Dm / 128, BT / 128, 1), 128, SMEM_REQ>>>(
        0, op_t, pt_t, ctx_b, sign_b1, aux_b1, dig_b1);

    // 4. LN + GELU -> fp16 context
    ln_gelu_ctx<<<BT, 256>>>(ctx_g, ctx_beta);

    // 5. all 8 head GEMMs: [16384,1024] x [1024,512] x8  (fp16 mma.sync)
    mma_gemm<<<dim3(DHv / 128, BT / 128, NHEAD), 128, SMEM_REQ>>>(
        1, op_t, pt_t, ctx_b, sign_b1, aux_b1, dig_b1);

    // 6. LN(512)+GELU + 512->oc projections, fused per-row warps
    head_final<<<dim3(BT / 8, NHEAD), 256>>>(
        sign_g, sign_beta, sign_w2, sign_b2,
        dig_g, dig_beta, dig_w2, dig_b2,
        aux_w2, aux_b2, out);
}

// round 14
// speedup vs baseline: 1.0758x; 1.0758x over previous
#include <cuda_runtime.h>
#include <cuda_fp16.h>
#include <math.h>
#include <stdint.h>

// Problem constants
#define Dm    1024
#define DQv   256
#define DHv   512
#define Pp    6
#define BATCH 8
#define Tt    2048
#define BT    (BATCH*Tt)       // 16384
#define NHEAD 8                // sign, aux, 6 digit heads
#define HBW   (NHEAD*DHv)      // 4096

// ------------------- scratch (static device globals; no cudaMalloc) -------
__device__ float  g_ctx[(size_t)BT * Dm];        // 64 MiB  (pre-LN fp32 context)
__device__ __half g_ctxh[(size_t)BT * Dm];       // 32 MiB  (post-LN fp16 context)
__device__ __half g_hidh[(size_t)BT * Dm];       // 32 MiB  (fp16 hidden)
__device__ __half g_hbig[(size_t)BT * HBW];      // 128 MiB (pre-LN head hidden, fp16)
__device__ float  g_opc[9 * Dm];
__device__ float  g_ptc[10 * Dm];
__device__ float  g_posc[Pp * DHv];
__device__ __half g_wctx_th[(size_t)Dm * Dm];    // ctx_w[0:1024,:]^T [N,K] fp16
__device__ __half g_whead_th[(size_t)NHEAD * DHv * Dm]; // W1' [512,1024] fp16

__device__ __forceinline__ float gelu_exact(float x) {
    return 0.5f * x * (1.0f + erff(x * 0.70710678118654752f));
}
__device__ __forceinline__ uint32_t smem_u32(const void* p) {
    uint32_t a;
    asm("{ .reg .u64 t; cvta.to.shared.u64 t, %1; cvt.u32.u64 %0, t; }" : "=r"(a) : "l"(p));
    return a;
}
__device__ __forceinline__ void cp16(uint32_t dst, const void* src) {
    asm volatile("cp.async.cg.shared.global [%0], [%1], 16;" :: "r"(dst), "l"(src));
}
#define CP_COMMIT() asm volatile("cp.async.commit_group;" ::: "memory")
#define CP_WAIT1()  asm volatile("cp.async.wait_group 1;" ::: "memory")
#define CP_WAIT0()  asm volatile("cp.async.wait_group 0;" ::: "memory")

__device__ __forceinline__ void mma_f16(float* c, const uint32_t* a, const uint32_t* b) {
    asm volatile("mma.sync.aligned.m16n8k16.row.col.f32.f16.f16.f32 "
        "{%0,%1,%2,%3}, {%4,%5,%6,%7}, {%8,%9}, {%0,%1,%2,%3};"
        : "+f"(c[0]), "+f"(c[1]), "+f"(c[2]), "+f"(c[3])
        : "r"(a[0]), "r"(a[1]), "r"(a[2]), "r"(a[3]), "r"(b[0]), "r"(b[1]));
}
__device__ __forceinline__ void ldm_x4(uint32_t& r0, uint32_t& r1, uint32_t& r2,
                                       uint32_t& r3, uint32_t addr) {
    asm volatile("ldmatrix.sync.aligned.m8n8.x4.shared.b16 {%0,%1,%2,%3}, [%4];"
        : "=r"(r0), "=r"(r1), "=r"(r2), "=r"(r3) : "r"(addr));
}

// ------------------- precompute embedding contributions -------------------
__global__ void precompute_kernel(const float* __restrict__ op_embed,
                                  const float* __restrict__ pt_embed,
                                  const float* __restrict__ pos_embed,
                                  const float* __restrict__ ctx_w,
                                  const float* __restrict__ dig_w1) {
    int idx = blockIdx.x * blockDim.x + threadIdx.x;
    if (idx < 9 * Dm) {
        int i = idx >> 10, n = idx & (Dm - 1);
        float s = 0.f;
        #pragma unroll 4
        for (int q = 0; q < DQv; q++)
            s += op_embed[i * DQv + q] * ctx_w[(size_t)(Dm + q) * Dm + n];
        g_opc[idx] = s;
    } else if (idx < 19 * Dm) {
        int j = idx - 9 * Dm;
        int i = j >> 10, n = j & (Dm - 1);
        float s = 0.f;
        #pragma unroll 4
        for (int q = 0; q < DQv; q++)
            s += pt_embed[i * DQv + q] * ctx_w[(size_t)(Dm + DQv + q) * Dm + n];
        g_ptc[j] = s;
    } else if (idx < 19 * Dm + Pp * DHv) {
        int j = idx - 19 * Dm;
        int p = j >> 9, h = j & (DHv - 1);
        float s = 0.f;
        #pragma unroll 4
        for (int q = 0; q < DQv; q++)
            s += pos_embed[p * DQv + q] * dig_w1[(size_t)p * 1280 * DHv + (size_t)(Dm + q) * DHv + h];
        g_posc[j] = s;
    }
}

// ------------------- round hidden to fp16 ---------------------------------
__global__ __launch_bounds__(256) void round_hidden(const float* __restrict__ hidden) {
    size_t i = (size_t)(blockIdx.x * 256 + threadIdx.x) * 4;
    float4 v = *(const float4*)(hidden + i);
    __half2* dst = (__half2*)(g_hidh + i);
    dst[0] = __floats2half2_rn(v.x, v.y);
    dst[1] = __floats2half2_rn(v.z, v.w);
}

// ------------------- weight transpose: [K=1024, N] -> [N, K] fp16 ---------
__global__ __launch_bounds__(256) void transpose_w(const float* __restrict__ ctx_w,
                                                   const float* __restrict__ sign_w1,
                                                   const float* __restrict__ aux_w1,
                                                   const float* __restrict__ dig_w1) {
    __shared__ float tbuf[32][33];
    int mat = blockIdx.z;
    const float* src; __half* dst; int ncols;
    if (mat == 0)      { src = ctx_w;   dst = g_wctx_th;                     ncols = Dm; }
    else if (mat == 1) { src = sign_w1; dst = g_whead_th;                    ncols = DHv; }
    else if (mat == 2) { src = aux_w1;  dst = g_whead_th + (size_t)DHv * Dm; ncols = DHv; }
    else {
        int p = mat - 3;
        src = dig_w1 + (size_t)p * 1280 * DHv;
        dst = g_whead_th + (size_t)(2 + p) * DHv * Dm;
        ncols = DHv;
    }
    int n0 = blockIdx.x * 32;
    int k0 = blockIdx.y * 32;
    if (n0 >= ncols) return;
    #pragma unroll
    for (int j = 0; j < 4; j++)
        tbuf[threadIdx.y + j * 8][threadIdx.x] =
            src[(size_t)(k0 + threadIdx.y + j * 8) * ncols + n0 + threadIdx.x];
    __syncthreads();
    #pragma unroll
    for (int j = 0; j < 4; j++) {
        float v = tbuf[threadIdx.x][threadIdx.y + j * 8];
        dst[(size_t)(n0 + threadIdx.y + j * 8) * Dm + k0 + threadIdx.x] = __float2half_rn(v);
    }
}

// ------------------- fp16 mma.sync GEMM, K-tile 64, 2-stage cp.async ------
// 128x128 block, 4 warps, 64x64/warp.  mode 0: grid (8,128,1)  mode 1: (4,128,8)
#define NKT 16
#define LDHB 144                       // bytes per smem row (64 halves + 16B pad)
#define ATILE_B (128 * LDHB)           // 18432 B per operand per stage
#define STAGE_B (2 * ATILE_B)          // 36864 B

__global__ __launch_bounds__(128, 2) void mma_gemm(int mode,
                                                   const int* __restrict__ op_t,
                                                   const int* __restrict__ pt_t,
                                                   const float* __restrict__ ctx_b,
                                                   const float* __restrict__ sign_b1,
                                                   const float* __restrict__ aux_b1,
                                                   const float* __restrict__ dig_b1) {
    extern __shared__ char smem[];
    uint32_t sbase = smem_u32(smem);

    int tid = threadIdx.x;
    int wid = tid >> 5, lane = tid & 31;
    int grp = lane >> 2, thr = lane & 3;
    int li = lane & 7, lm = lane >> 3;   // ldmatrix row index / matrix index
    int wm = (wid >> 1) * 64, wn = (wid & 1) * 64;
    int bn = blockIdx.x * 128, bm = blockIdx.y * 128, z = blockIdx.z;

    const __half* Aptr = (mode == 0 ? g_hidh : g_ctxh) + (size_t)bm * Dm;
    const __half* Bptr = (mode == 0 ? g_wctx_th : g_whead_th + (size_t)z * DHv * Dm)
                         + (size_t)bn * Dm;

    float acc[4][8][4];
    #pragma unroll
    for (int a = 0; a < 4; a++)
        #pragma unroll
        for (int b = 0; b < 8; b++)
            #pragma unroll
            for (int c = 0; c < 4; c++) acc[a][b][c] = 0.f;

    // preload stage 0 (64-wide K tile: 128 rows x 8 chunks of 16B per operand)
    {
        uint32_t sA = sbase, sB = sbase + ATILE_B;
        #pragma unroll
        for (int j = 0; j < 8; j++) {
            int idx = tid + j * 128;
            int r = idx >> 3, c = idx & 7;
            cp16(sA + (uint32_t)(r * LDHB + c * 16), Aptr + (size_t)r * Dm + c * 8);
            cp16(sB + (uint32_t)(r * LDHB + c * 16), Bptr + (size_t)r * Dm + c * 8);
        }
        CP_COMMIT();
    }

    for (int kt = 0; kt < NKT; kt++) {
        int buf = kt & 1;
        if (kt + 1 < NKT) {
            int k0 = (kt + 1) * 64;
            uint32_t sA = sbase + (uint32_t)(buf ^ 1) * STAGE_B;
            uint32_t sB = sA + ATILE_B;
            #pragma unroll
            for (int j = 0; j < 8; j++) {
                int idx = tid + j * 128;
                int r = idx >> 3, c = idx & 7;
                cp16(sA + (uint32_t)(r * LDHB + c * 16), Aptr + (size_t)r * Dm + k0 + c * 8);
                cp16(sB + (uint32_t)(r * LDHB + c * 16), Bptr + (size_t)r * Dm + k0 + c * 8);
            }
            CP_COMMIT();
            CP_WAIT1();
        } else {
            CP_WAIT0();
        }
        __syncthreads();

        uint32_t Ab = sbase + (uint32_t)buf * STAGE_B;
        uint32_t Bb = Ab + ATILE_B;
        #pragma unroll
        for (int s = 0; s < 4; s++) {          // four k16 steps per kt
            int kbase = s * 32;                 // byte offset of k-chunk (16 halves)
            uint32_t bf[8][2];
            #pragma unroll
            for (int p = 0; p < 4; p++) {
                int in0 = 2 * p;
                uint32_t addr = Bb + (uint32_t)((wn + (in0 + (lm >> 1)) * 8 + li) * LDHB
                                                + kbase + (lm & 1) * 16);
                ldm_x4(bf[in0][0], bf[in0][1], bf[in0 + 1][0], bf[in0 + 1][1], addr);
            }
            #pragma unroll
            for (int im = 0; im < 4; im++) {
                int rb = wm + im * 16;
                uint32_t af[4];
                uint32_t addr = Ab + (uint32_t)((rb + (lm & 1) * 8 + li) * LDHB
                                                + kbase + (lm >> 1) * 16);
                ldm_x4(af[0], af[1], af[2], af[3], addr);
                #pragma unroll
                for (int in = 0; in < 8; in++)
                    mma_f16(acc[im][in], af, bf[in]);
            }
        }
        __syncthreads();
    }

    // ---- epilogue ----
    const float* b1 = nullptr; const float* posc = nullptr;
    if (mode == 1) {
        if (z == 0)      b1 = sign_b1;
        else if (z == 1) b1 = aux_b1;
        else { b1 = dig_b1 + (z - 2) * DHv; posc = g_posc + (z - 2) * DHv; }
    }
    #pragma unroll
    for (int im = 0; im < 4; im++) {
        #pragma unroll
        for (int half = 0; half < 2; half++) {
            int row = bm + wm + im * 16 + grp + half * 8;
            if (mode == 0) {
                int op = op_t[row >> 11];
                int pt = pt_t[row];
                const float* ocp = g_opc + op * Dm + bn;
                const float* pcp = g_ptc + pt * Dm + bn;
                const float* bpv = ctx_b + bn;
                float* dst = g_ctx + (size_t)row * Dm + bn;
                #pragma unroll
                for (int in = 0; in < 8; in++) {
                    int cl = wn + in * 8 + 2 * thr;
                    float2 v;
                    v.x = acc[im][in][half * 2 + 0] + ocp[cl]     + pcp[cl]     + bpv[cl];
                    v.y = acc[im][in][half * 2 + 1] + ocp[cl + 1] + pcp[cl + 1] + bpv[cl + 1];
                    *(float2*)(dst + cl) = v;
                }
            } else {
                __half* dst = g_hbig + (size_t)row * HBW + z * DHv + bn;
                #pragma unroll
                for (int in = 0; in < 8; in++) {
                    int cl = wn + in * 8 + 2 * thr;
                    int col = bn + cl;
                    float vx = acc[im][in][half * 2 + 0] + b1[col];
                    float vy = acc[im][in][half * 2 + 1] + b1[col + 1];
                    if (posc) { vx += posc[col]; vy += posc[col + 1]; }
                    *(__half2*)(dst + cl) = __floats2half2_rn(vx, vy);
                }
            }
        }
    }
}

// ------------------- LN(1024) + GELU : g_ctx (fp32) -> g_ctxh (fp16) ------
__global__ __launch_bounds__(256) void ln_gelu_ctx(const float* __restrict__ g,
                                                   const float* __restrict__ beta) {
    int row = blockIdx.x;
    int tid = threadIdx.x;
    int lane = tid & 31, wid = tid >> 5;
    const float* base = g_ctx + (size_t)row * Dm;
    float4 v = *(const float4*)&base[tid * 4];
    float s  = v.x + v.y + v.z + v.w;
    float ss = v.x * v.x + v.y * v.y + v.z * v.z + v.w * v.w;
    #pragma unroll
    for (int off = 16; off; off >>= 1) {
        s  += __shfl_xor_sync(0xffffffffu, s, off);
        ss += __shfl_xor_sync(0xffffffffu, ss, off);
    }
    __shared__ float sh_s[8], sh_ss[8];
    if (lane == 0) { sh_s[wid] = s; sh_ss[wid] = ss; }
    __syncthreads();
    if (tid == 0) {
        float a = 0.f, b2 = 0.f;
        #pragma unroll
        for (int i = 0; i < 8; i++) { a += sh_s[i]; b2 += sh_ss[i]; }
        sh_s[0] = a; sh_ss[0] = b2;
    }
    __syncthreads();
    float mean = sh_s[0] * (1.f / Dm);
    float var  = sh_ss[0] * (1.f / Dm) - mean * mean;
    float rstd = rsqrtf(var + 1e-5f);
    int c = tid * 4;
    float o0 = gelu_exact((v.x - mean) * rstd * g[c + 0] + beta[c + 0]);
    float o1 = gelu_exact((v.y - mean) * rstd * g[c + 1] + beta[c + 1]);
    float o2 = gelu_exact((v.z - mean) * rstd * g[c + 2] + beta[c + 2]);
    float o3 = gelu_exact((v.w - mean) * rstd * g[c + 3] + beta[c + 3]);
    __half2* dst = (__half2*)(g_ctxh + (size_t)row * Dm + c);
    dst[0] = __floats2half2_rn(o0, o1);
    dst[1] = __floats2half2_rn(o2, o3);
}

// ------------------- final: LN(512)+GELU + tiny GEMM (512 -> oc), fused ---
// 64 rows per block (each of 8 warps loops over 8 rows); w2 staged ONCE/block.
__global__ __launch_bounds__(256) void head_final(const float* __restrict__ sign_g,
                                                  const float* __restrict__ sign_beta,
                                                  const float* __restrict__ sign_w2,
                                                  const float* __restrict__ sign_b2,
                                                  const float* __restrict__ dig_g,
                                                  const float* __restrict__ dig_beta,
                                                  const float* __restrict__ dig_w2,
                                                  const float* __restrict__ dig_b2,
                                                  const float* __restrict__ aux_w2,
                                                  const float* __restrict__ aux_b2,
                                                  float* __restrict__ out) {
    int head = blockIdx.y;
    int oc; bool ln;
    const float *g = nullptr, *bt = nullptr, *w2, *b2;
    if (head == 0)      { oc = 3;  ln = true;  g = sign_g; bt = sign_beta; w2 = sign_w2; b2 = sign_b2; }
    else if (head == 1) { oc = 1;  ln = false; w2 = aux_w2; b2 = aux_b2; }
    else {
        int p = head - 2;
        oc = 10; ln = true;
        g = dig_g + p * DHv; bt = dig_beta + p * DHv;
        w2 = dig_w2 + (size_t)p * DHv * 10; b2 = dig_b2 + p * 10;
    }

    __shared__ float w2s[10 * DHv];
    for (int i = threadIdx.x; i < DHv * oc; i += 256) {
        int k = i / oc, o = i - k * oc;
        w2s[o * DHv + k] = w2[i];
    }
    __syncthreads();

    int wid = threadIdx.x >> 5, lane = threadIdx.x & 31;

    for (int it = 0; it < 8; it++) {
        int row = blockIdx.x * 64 + wid * 8 + it;
        const __half* hb = g_hbig + (size_t)row * HBW + head * DHv;

        float v[16];
        #pragma unroll
        for (int j = 0; j < 16; j++)
            v[j] = __half2float(hb[lane + 32 * j]);

        float mean = 0.f, rstd = 1.f;
        if (ln) {
            float s = 0.f, ss = 0.f;
            #pragma unroll
            for (int j = 0; j < 16; j++) { s += v[j]; ss += v[j] * v[j]; }
            #pragma unroll
            for (int off = 16; off; off >>= 1) {
                s  += __shfl_xor_sync(0xffffffffu, s, off);
                ss += __shfl_xor_sync(0xffffffffu, ss, off);
            }
            mean = s * (1.f / DHv);
            float var = ss * (1.f / DHv) - mean * mean;
            rstd = rsqrtf(var + 1e-5f);
        }

        float psum[10];
        #pragma unroll
        for (int o = 0; o < 10; o++) psum[o] = 0.f;

        #pragma unroll
        for (int j = 0; j < 16; j++) {
            int k = lane + 32 * j;
            float x = v[j];
            if (ln) x = (x - mean) * rstd * g[k] + bt[k];
            x = gelu_exact(x);
            #pragma unroll
            for (int o = 0; o < 10; o++)
                if (o < oc) psum[o] = fmaf(x, w2s[o * DHv + k], psum[o]);
        }
        #pragma unroll
        for (int o = 0; o < 10; o++)
            if (o < oc)
                #pragma unroll
                for (int off = 16; off; off >>= 1)
                    psum[o] += __shfl_xor_sync(0xffffffffu, psum[o], off);

        if (lane == 0) {
            if (head == 0) {
                for (int o = 0; o < 3; o++) out[(size_t)row * 3 + o] = psum[o] + b2[o];
            } else if (head == 1) {
                out[(size_t)BT * 63 + row] = psum[0] + b2[0];
            } else {
                int p = head - 2;
                for (int o = 0; o < 10; o++)
                    out[(size_t)BT * 3 + (size_t)row * 60 + p * 10 + o] = psum[o] + b2[o];
            }
        }
    }
}

// ------------------- launch ------------------------------------------------
extern "C" void kernel_launch(void* const* d_in, const int* in_sizes, int n_in,
                              void* d_out, int out_size) {
    const float* hidden    = (const float*)d_in[0];
    const int*   op_t      = (const int*)  d_in[1];
    const int*   pt_t      = (const int*)  d_in[2];
    const float* op_embed  = (const float*)d_in[3];
    const float* pt_embed  = (const float*)d_in[4];
    const float* pos_embed = (const float*)d_in[5];
    const float* ctx_w     = (const float*)d_in[6];
    const float* ctx_b     = (const float*)d_in[7];
    const float* ctx_g     = (const float*)d_in[8];
    const float* ctx_beta  = (const float*)d_in[9];
    const float* sign_w1   = (const float*)d_in[10];
    const float* sign_b1   = (const float*)d_in[11];
    const float* sign_g    = (const float*)d_in[12];
    const float* sign_beta = (const float*)d_in[13];
    const float* sign_w2   = (const float*)d_in[14];
    const float* sign_b2   = (const float*)d_in[15];
    const float* dig_w1    = (const float*)d_in[16];
    const float* dig_b1    = (const float*)d_in[17];
    const float* dig_g     = (const float*)d_in[18];
    const float* dig_beta  = (const float*)d_in[19];
    const float* dig_w2    = (const float*)d_in[20];
    const float* dig_b2    = (const float*)d_in[21];
    const float* aux_w1    = (const float*)d_in[22];
    const float* aux_b1    = (const float*)d_in[23];
    const float* aux_w2    = (const float*)d_in[24];
    const float* aux_b2    = (const float*)d_in[25];
    float* out = (float*)d_out;

    const int SMEM_REQ = 2 * STAGE_B;   // 73728 B
    static int attr_set = 0;
    if (!attr_set) {
        cudaFuncSetAttribute(mma_gemm, cudaFuncAttributeMaxDynamicSharedMemorySize, SMEM_REQ);
        attr_set = 1;
    }

    // 1. embedding-contribution precompute (tiny)
    precompute_kernel<<<(19 * Dm + Pp * DHv + 255) / 256, 256>>>(
        op_embed, pt_embed, pos_embed, ctx_w, dig_w1);

    // 2. weight transpose -> K-major fp16 + round hidden to fp16
    transpose_w<<<dim3(32, 32, 9), dim3(32, 8)>>>(ctx_w, sign_w1, aux_w1, dig_w1);
    round_hidden<<<(BT * Dm / 4) / 256, 256>>>(hidden);

    // 3. context GEMM (pre-LN): [16384,1024] x [1024,1024]  (fp16 mma.sync)
    mma_gemm<<<dim3(Dm / 128, BT / 128, 1), 128, SMEM_REQ>>>(
        0, op_t, pt_t, ctx_b, sign_b1, aux_b1, dig_b1);

    // 4. LN + GELU -> fp16 context
    ln_gelu_ctx<<<BT, 256>>>(ctx_g, ctx_beta);

    // 5. all 8 head GEMMs: [16384,1024] x [1024,512] x8  (fp16 mma.sync)
    mma_gemm<<<dim3(DHv / 128, BT / 128, NHEAD), 128, SMEM_REQ>>>(
        1, op_t, pt_t, ctx_b, sign_b1, aux_b1, dig_b1);

    // 6. LN(512)+GELU + 512->oc projections: 64 rows/block, w2 staged once
    head_final<<<dim3(BT / 64, NHEAD), 256>>>(
        sign_g, sign_beta, sign_w2, sign_b2,
        dig_g, dig_beta, dig_w2, dig_b2,
        aux_w2, aux_b2, out);
}

// round 15
// speedup vs baseline: 1.0896x; 1.0128x over previous
#include <cuda_runtime.h>
#include <cuda_fp16.h>
#include <math.h>
#include <stdint.h>

// Problem constants
#define Dm    1024
#define DQv   256
#define DHv   512
#define Pp    6
#define BATCH 8
#define Tt    2048
#define BT    (BATCH*Tt)       // 16384
#define NHEAD 8                // sign, aux, 6 digit heads
#define HBW   (NHEAD*DHv)      // 4096

// ------------------- scratch (static device globals; no cudaMalloc) -------
__device__ float  g_ctx[(size_t)BT * Dm];        // 64 MiB  (pre-LN fp32 context)
__device__ __half g_ctxh[(size_t)BT * Dm];       // 32 MiB  (post-LN fp16 context)
__device__ __half g_hidh[(size_t)BT * Dm];       // 32 MiB  (fp16 hidden)
__device__ __half g_hbig[(size_t)BT * HBW];      // 128 MiB (pre-LN head hidden, fp16)
__device__ float  g_opc[9 * Dm];                 // op contribution + ctx_b folded
__device__ float  g_ptc[10 * Dm];
__device__ float  g_bhead[HBW];                  // per-head b1 (+posc) combined
__device__ __half g_wctx_th[(size_t)Dm * Dm];    // ctx_w[0:1024,:]^T [N,K] fp16
__device__ __half g_whead_th[(size_t)NHEAD * DHv * Dm]; // W1' [4096,1024] fp16

__device__ __forceinline__ float gelu_exact(float x) {
    return 0.5f * x * (1.0f + erff(x * 0.70710678118654752f));
}
__device__ __forceinline__ uint32_t smem_u32(const void* p) {
    uint32_t a;
    asm("{ .reg .u64 t; cvta.to.shared.u64 t, %1; cvt.u32.u64 %0, t; }" : "=r"(a) : "l"(p));
    return a;
}
__device__ __forceinline__ void cp16(uint32_t dst, const void* src) {
    asm volatile("cp.async.cg.shared.global [%0], [%1], 16;" :: "r"(dst), "l"(src));
}
#define CP_COMMIT() asm volatile("cp.async.commit_group;" ::: "memory")
#define CP_WAIT1()  asm volatile("cp.async.wait_group 1;" ::: "memory")
#define CP_WAIT0()  asm volatile("cp.async.wait_group 0;" ::: "memory")

__device__ __forceinline__ void mma_f16(float* c, const uint32_t* a, const uint32_t* b) {
    asm volatile("mma.sync.aligned.m16n8k16.row.col.f32.f16.f16.f32 "
        "{%0,%1,%2,%3}, {%4,%5,%6,%7}, {%8,%9}, {%0,%1,%2,%3};"
        : "+f"(c[0]), "+f"(c[1]), "+f"(c[2]), "+f"(c[3])
        : "r"(a[0]), "r"(a[1]), "r"(a[2]), "r"(a[3]), "r"(b[0]), "r"(b[1]));
}
__device__ __forceinline__ void ldm_x4(uint32_t& r0, uint32_t& r1, uint32_t& r2,
                                       uint32_t& r3, uint32_t addr) {
    asm volatile("ldmatrix.sync.aligned.m8n8.x4.shared.b16 {%0,%1,%2,%3}, [%4];"
        : "=r"(r0), "=r"(r1), "=r"(r2), "=r"(r3) : "r"(addr));
}

// ------------------- fused prep: embeddings + bias fold + transpose + round
// block ranges: [0, NB_A) scalar precompute; [NB_A, NB_A+NB_B) transpose;
//               [NB_A+NB_B, ...) round hidden.
#define NB_A ((19 * Dm + HBW + 255) / 256)   // 92
#define NB_B (9 * 1024)                      // transpose tiles (32x32 each)
#define NB_C (BT * Dm / 4 / 256)             // 16384

__global__ __launch_bounds__(256) void prep_kernel(const float* __restrict__ hidden,
                                                   const float* __restrict__ op_embed,
                                                   const float* __restrict__ pt_embed,
                                                   const float* __restrict__ pos_embed,
                                                   const float* __restrict__ ctx_w,
                                                   const float* __restrict__ ctx_b,
                                                   const float* __restrict__ sign_w1,
                                                   const float* __restrict__ sign_b1,
                                                   const float* __restrict__ aux_w1,
                                                   const float* __restrict__ aux_b1,
                                                   const float* __restrict__ dig_w1,
                                                   const float* __restrict__ dig_b1) {
    int bx = blockIdx.x;
    int tid = threadIdx.x;

    if (bx < NB_A) {
        int idx = bx * 256 + tid;
        if (idx < 9 * Dm) {
            int i = idx >> 10, n = idx & (Dm - 1);
            float s = ctx_b[n];                       // fold ctx_b into op contribution
            #pragma unroll 4
            for (int q = 0; q < DQv; q++)
                s += op_embed[i * DQv + q] * ctx_w[(size_t)(Dm + q) * Dm + n];
            g_opc[idx] = s;
        } else if (idx < 19 * Dm) {
            int j = idx - 9 * Dm;
            int i = j >> 10, n = j & (Dm - 1);
            float s = 0.f;
            #pragma unroll 4
            for (int q = 0; q < DQv; q++)
                s += pt_embed[i * DQv + q] * ctx_w[(size_t)(Dm + DQv + q) * Dm + n];
            g_ptc[j] = s;
        } else if (idx < 19 * Dm + HBW) {
            int j = idx - 19 * Dm;
            int z = j >> 9, h = j & (DHv - 1);
            float s;
            if (z == 0)      s = sign_b1[h];
            else if (z == 1) s = aux_b1[h];
            else {
                int p = z - 2;
                s = dig_b1[p * DHv + h];
                #pragma unroll 4
                for (int q = 0; q < DQv; q++)
                    s += pos_embed[p * DQv + q]
                       * dig_w1[(size_t)p * 1280 * DHv + (size_t)(Dm + q) * DHv + h];
            }
            g_bhead[j] = s;
        }
        return;
    }
    if (bx < NB_A + NB_B) {
        // transpose: [K=1024, ncols] -> [ncols, K] fp16
        __shared__ float tbuf[32][33];
        int gx = bx - NB_A;
        int mat = gx >> 10;              // /1024
        int rem = gx & 1023;
        int n0 = (rem & 31) * 32;
        int k0 = (rem >> 5) * 32;
        const float* src; __half* dst; int ncols;
        if (mat == 0)      { src = ctx_w;   dst = g_wctx_th;                     ncols = Dm; }
        else if (mat == 1) { src = sign_w1; dst = g_whead_th;                    ncols = DHv; }
        else if (mat == 2) { src = aux_w1;  dst = g_whead_th + (size_t)DHv * Dm; ncols = DHv; }
        else {
            int p = mat - 3;
            src = dig_w1 + (size_t)p * 1280 * DHv;
            dst = g_whead_th + (size_t)(2 + p) * DHv * Dm;
            ncols = DHv;
        }
        if (n0 >= ncols) return;
        int tx = tid & 31, ty = tid >> 5;   // 32 x 8
        #pragma unroll
        for (int j = 0; j < 4; j++)
            tbuf[ty + j * 8][tx] = src[(size_t)(k0 + ty + j * 8) * ncols + n0 + tx];
        __syncthreads();
        #pragma unroll
        for (int j = 0; j < 4; j++) {
            float v = tbuf[tx][ty + j * 8];
            dst[(size_t)(n0 + ty + j * 8) * Dm + k0 + tx] = __float2half_rn(v);
        }
        return;
    }
    // round hidden to fp16
    {
        int gx = bx - NB_A - NB_B;
        size_t i = (size_t)(gx * 256 + tid) * 4;
        float4 v = *(const float4*)(hidden + i);
        __half2* dst = (__half2*)(g_hidh + i);
        dst[0] = __floats2half2_rn(v.x, v.y);
        dst[1] = __floats2half2_rn(v.z, v.w);
    }
}

// ------------------- fp16 mma.sync GEMM, K-tile 64, 2-stage cp.async ------
// 128x128 block, 4 warps, 64x64/warp. mode 0: grid (8,128)  mode 1: (32,128)
#define NKT 16
#define LDHB 144                       // bytes per smem row (64 halves + 16B pad)
#define ATILE_B (128 * LDHB)           // 18432 B per operand per stage
#define STAGE_B (2 * ATILE_B)          // 36864 B

__global__ __launch_bounds__(128, 2) void mma_gemm(int mode,
                                                   const int* __restrict__ op_t,
                                                   const int* __restrict__ pt_t) {
    extern __shared__ char smem[];
    uint32_t sbase = smem_u32(smem);

    int tid = threadIdx.x;
    int wid = tid >> 5, lane = tid & 31;
    int grp = lane >> 2, thr = lane & 3;
    int li = lane & 7, lm = lane >> 3;   // ldmatrix row index / matrix index
    int wm = (wid >> 1) * 64, wn = (wid & 1) * 64;
    int bn = blockIdx.x * 128, bm = blockIdx.y * 128;

    const __half* Aptr = (mode == 0 ? g_hidh : g_ctxh) + (size_t)bm * Dm;
    const __half* Bptr = (mode == 0 ? g_wctx_th : g_whead_th) + (size_t)bn * Dm;

    float acc[4][8][4];
    #pragma unroll
    for (int a = 0; a < 4; a++)
        #pragma unroll
        for (int b = 0; b < 8; b++)
            #pragma unroll
            for (int c = 0; c < 4; c++) acc[a][b][c] = 0.f;

    // preload stage 0 (64-wide K tile: 128 rows x 8 chunks of 16B per operand)
    {
        uint32_t sA = sbase, sB = sbase + ATILE_B;
        #pragma unroll
        for (int j = 0; j < 8; j++) {
            int idx = tid + j * 128;
            int r = idx >> 3, c = idx & 7;
            cp16(sA + (uint32_t)(r * LDHB + c * 16), Aptr + (size_t)r * Dm + c * 8);
            cp16(sB + (uint32_t)(r * LDHB + c * 16), Bptr + (size_t)r * Dm + c * 8);
        }
        CP_COMMIT();
    }

    for (int kt = 0; kt < NKT; kt++) {
        int buf = kt & 1;
        if (kt + 1 < NKT) {
            int k0 = (kt + 1) * 64;
            uint32_t sA = sbase + (uint32_t)(buf ^ 1) * STAGE_B;
            uint32_t sB = sA + ATILE_B;
            #pragma unroll
            for (int j = 0; j < 8; j++) {
                int idx = tid + j * 128;
                int r = idx >> 3, c = idx & 7;
                cp16(sA + (uint32_t)(r * LDHB + c * 16), Aptr + (size_t)r * Dm + k0 + c * 8);
                cp16(sB + (uint32_t)(r * LDHB + c * 16), Bptr + (size_t)r * Dm + k0 + c * 8);
            }
            CP_COMMIT();
            CP_WAIT1();
        } else {
            CP_WAIT0();
        }
        __syncthreads();

        uint32_t Ab = sbase + (uint32_t)buf * STAGE_B;
        uint32_t Bb = Ab + ATILE_B;
        #pragma unroll
        for (int s = 0; s < 4; s++) {          // four k16 steps per kt
            int kbase = s * 32;                 // byte offset of k-chunk (16 halves)
            uint32_t bf[8][2];
            #pragma unroll
            for (int p = 0; p < 4; p++) {
                int in0 = 2 * p;
                uint32_t addr = Bb + (uint32_t)((wn + (in0 + (lm >> 1)) * 8 + li) * LDHB
                                                + kbase + (lm & 1) * 16);
                ldm_x4(bf[in0][0], bf[in0][1], bf[in0 + 1][0], bf[in0 + 1][1], addr);
            }
            #pragma unroll
            for (int im = 0; im < 4; im++) {
                int rb = wm + im * 16;
                uint32_t af[4];
                uint32_t addr = Ab + (uint32_t)((rb + (lm & 1) * 8 + li) * LDHB
                                                + kbase + (lm >> 1) * 16);
                ldm_x4(af[0], af[1], af[2], af[3], addr);
                #pragma unroll
                for (int in = 0; in < 8; in++)
                    mma_f16(acc[im][in], af, bf[in]);
            }
        }
        __syncthreads();
    }

    // ---- epilogue ----
    #pragma unroll
    for (int im = 0; im < 4; im++) {
        #pragma unroll
        for (int half = 0; half < 2; half++) {
            int row = bm + wm + im * 16 + grp + half * 8;
            if (mode == 0) {
                int op = op_t[row >> 11];
                int pt = pt_t[row];
                const float* ocp = g_opc + op * Dm + bn;   // includes ctx_b
                const float* pcp = g_ptc + pt * Dm + bn;
                float* dst = g_ctx + (size_t)row * Dm + bn;
                #pragma unroll
                for (int in = 0; in < 8; in++) {
                    int cl = wn + in * 8 + 2 * thr;
                    float2 v;
                    v.x = acc[im][in][half * 2 + 0] + ocp[cl]     + pcp[cl];
                    v.y = acc[im][in][half * 2 + 1] + ocp[cl + 1] + pcp[cl + 1];
                    *(float2*)(dst + cl) = v;
                }
            } else {
                __half* dst = g_hbig + (size_t)row * HBW + bn;
                const float* bh = g_bhead + bn;
                #pragma unroll
                for (int in = 0; in < 8; in++) {
                    int cl = wn + in * 8 + 2 * thr;
                    float vx = acc[im][in][half * 2 + 0] + bh[cl];
                    float vy = acc[im][in][half * 2 + 1] + bh[cl + 1];
                    *(__half2*)(dst + cl) = __floats2half2_rn(vx, vy);
                }
            }
        }
    }
}

// ------------------- LN(1024) + GELU : g_ctx (fp32) -> g_ctxh (fp16) ------
__global__ __launch_bounds__(256) void ln_gelu_ctx(const float* __restrict__ g,
                                                   const float* __restrict__ beta) {
    int row = blockIdx.x;
    int tid = threadIdx.x;
    int lane = tid & 31, wid = tid >> 5;
    const float* base = g_ctx + (size_t)row * Dm;
    float4 v = *(const float4*)&base[tid * 4];
    float s  = v.x + v.y + v.z + v.w;
    float ss = v.x * v.x + v.y * v.y + v.z * v.z + v.w * v.w;
    #pragma unroll
    for (int off = 16; off; off >>= 1) {
        s  += __shfl_xor_sync(0xffffffffu, s, off);
        ss += __shfl_xor_sync(0xffffffffu, ss, off);
    }
    __shared__ float sh_s[8], sh_ss[8];
    if (lane == 0) { sh_s[wid] = s; sh_ss[wid] = ss; }
    __syncthreads();
    if (tid == 0) {
        float a = 0.f, b2 = 0.f;
        #pragma unroll
        for (int i = 0; i < 8; i++) { a += sh_s[i]; b2 += sh_ss[i]; }
        sh_s[0] = a; sh_ss[0] = b2;
    }
    __syncthreads();
    float mean = sh_s[0] * (1.f / Dm);
    float var  = sh_ss[0] * (1.f / Dm) - mean * mean;
    float rstd = rsqrtf(var + 1e-5f);
    int c = tid * 4;
    float o0 = gelu_exact((v.x - mean) * rstd * g[c + 0] + beta[c + 0]);
    float o1 = gelu_exact((v.y - mean) * rstd * g[c + 1] + beta[c + 1]);
    float o2 = gelu_exact((v.z - mean) * rstd * g[c + 2] + beta[c + 2]);
    float o3 = gelu_exact((v.w - mean) * rstd * g[c + 3] + beta[c + 3]);
    __half2* dst = (__half2*)(g_ctxh + (size_t)row * Dm + c);
    dst[0] = __floats2half2_rn(o0, o1);
    dst[1] = __floats2half2_rn(o2, o3);
}

// ------------------- final: LN(512)+GELU + tiny GEMM (512 -> oc), fused ---
// 128 rows per block (each of 8 warps loops over 16 rows); w2 staged ONCE.
__global__ __launch_bounds__(256) void head_final(const float* __restrict__ sign_g,
                                                  const float* __restrict__ sign_beta,
                                                  const float* __restrict__ sign_w2,
                                                  const float* __restrict__ sign_b2,
                                                  const float* __restrict__ dig_g,
                                                  const float* __restrict__ dig_beta,
                                                  const float* __restrict__ dig_w2,
                                                  const float* __restrict__ dig_b2,
                                                  const float* __restrict__ aux_w2,
                                                  const float* __restrict__ aux_b2,
                                                  float* __restrict__ out) {
    int head = blockIdx.y;
    int oc; bool ln;
    const float *g = nullptr, *bt = nullptr, *w2, *b2;
    if (head == 0)      { oc = 3;  ln = true;  g = sign_g; bt = sign_beta; w2 = sign_w2; b2 = sign_b2; }
    else if (head == 1) { oc = 1;  ln = false; w2 = aux_w2; b2 = aux_b2; }
    else {
        int p = head - 2;
        oc = 10; ln = true;
        g = dig_g + p * DHv; bt = dig_beta + p * DHv;
        w2 = dig_w2 + (size_t)p * DHv * 10; b2 = dig_b2 + p * 10;
    }

    __shared__ float w2s[10 * DHv];
    for (int i = threadIdx.x; i < DHv * oc; i += 256) {
        int k = i / oc, o = i - k * oc;
        w2s[o * DHv + k] = w2[i];
    }
    __syncthreads();

    int wid = threadIdx.x >> 5, lane = threadIdx.x & 31;

    for (int it = 0; it < 16; it++) {
        int row = blockIdx.x * 128 + wid * 16 + it;
        const __half* hb = g_hbig + (size_t)row * HBW + head * DHv;

        float v[16];
        #pragma unroll
        for (int j = 0; j < 16; j++)
            v[j] = __half2float(hb[lane + 32 * j]);

        float mean = 0.f, rstd = 1.f;
        if (ln) {
            float s = 0.f, ss = 0.f;
            #pragma unroll
            for (int j = 0; j < 16; j++) { s += v[j]; ss += v[j] * v[j]; }
            #pragma unroll
            for (int off = 16; off; off >>= 1) {
                s  += __shfl_xor_sync(0xffffffffu, s, off);
                ss += __shfl_xor_sync(0xffffffffu, ss, off);
            }
            mean = s * (1.f / DHv);
            float var = ss * (1.f / DHv) - mean * mean;
            rstd = rsqrtf(var + 1e-5f);
        }

        float psum[10];
        #pragma unroll
        for (int o = 0; o < 10; o++) psum[o] = 0.f;

        #pragma unroll
        for (int j = 0; j < 16; j++) {
            int k = lane + 32 * j;
            float x = v[j];
            if (ln) x = (x - mean) * rstd * g[k] + bt[k];
            x = gelu_exact(x);
            #pragma unroll
            for (int o = 0; o < 10; o++)
                if (o < oc) psum[o] = fmaf(x, w2s[o * DHv + k], psum[o]);
        }
        #pragma unroll
        for (int o = 0; o < 10; o++)
            if (o < oc)
                #pragma unroll
                for (int off = 16; off; off >>= 1)
                    psum[o] += __shfl_xor_sync(0xffffffffu, psum[o], off);

        if (lane == 0) {
            if (head == 0) {
                for (int o = 0; o < 3; o++) out[(size_t)row * 3 + o] = psum[o] + b2[o];
            } else if (head == 1) {
                out[(size_t)BT * 63 + row] = psum[0] + b2[0];
            } else {
                int p = head - 2;
                for (int o = 0; o < 10; o++)
                    out[(size_t)BT * 3 + (size_t)row * 60 + p * 10 + o] = psum[o] + b2[o];
            }
        }
    }
}

// ------------------- launch ------------------------------------------------
extern "C" void kernel_launch(void* const* d_in, const int* in_sizes, int n_in,
                              void* d_out, int out_size) {
    const float* hidden    = (const float*)d_in[0];
    const int*   op_t      = (const int*)  d_in[1];
    const int*   pt_t      = (const int*)  d_in[2];
    const float* op_embed  = (const float*)d_in[3];
    const float* pt_embed  = (const float*)d_in[4];
    const float* pos_embed = (const float*)d_in[5];
    const float* ctx_w     = (const float*)d_in[6];
    const float* ctx_b     = (const float*)d_in[7];
    const float* ctx_g     = (const float*)d_in[8];
    const float* ctx_beta  = (const float*)d_in[9];
    const float* sign_w1   = (const float*)d_in[10];
    const float* sign_b1   = (const float*)d_in[11];
    const float* sign_g    = (const float*)d_in[12];
    const float* sign_beta = (const float*)d_in[13];
    const float* sign_w2   = (const float*)d_in[14];
    const float* sign_b2   = (const float*)d_in[15];
    const float* dig_w1    = (const float*)d_in[16];
    const float* dig_b1    = (const float*)d_in[17];
    const float* dig_g     = (const float*)d_in[18];
    const float* dig_beta  = (const float*)d_in[19];
    const float* dig_w2    = (const float*)d_in[20];
    const float* dig_b2    = (const float*)d_in[21];
    const float* aux_w1    = (const float*)d_in[22];
    const float* aux_b1    = (const float*)d_in[23];
    const float* aux_w2    = (const float*)d_in[24];
    const float* aux_b2    = (const float*)d_in[25];
    float* out = (float*)d_out;

    const int SMEM_REQ = 2 * STAGE_B;   // 73728 B
    static int attr_set = 0;
    if (!attr_set) {
        cudaFuncSetAttribute(mma_gemm, cudaFuncAttributeMaxDynamicSharedMemorySize, SMEM_REQ);
        attr_set = 1;
    }

    // 1. fused prep: embedding contributions + bias folds + transpose + round
    prep_kernel<<<NB_A + NB_B + NB_C, 256>>>(
        hidden, op_embed, pt_embed, pos_embed, ctx_w, ctx_b,
        sign_w1, sign_b1, aux_w1, aux_b1, dig_w1, dig_b1);

    // 2. context GEMM (pre-LN): [16384,1024] x [1024,1024]  (fp16 mma.sync)
    mma_gemm<<<dim3(Dm / 128, BT / 128), 128, SMEM_REQ>>>(0, op_t, pt_t);

    // 3. LN + GELU -> fp16 context
    ln_gelu_ctx<<<BT, 256>>>(ctx_g, ctx_beta);

    // 4. all 8 head GEMMs as one [16384,1024]x[1024,4096]  (fp16 mma.sync)
    mma_gemm<<<dim3(HBW / 128, BT / 128), 128, SMEM_REQ>>>(1, op_t, pt_t);

    // 5. LN(512)+GELU + 512->oc projections: 128 rows/block, w2 staged once
    head_final<<<dim3(BT / 128, NHEAD), 256>>>(
        sign_g, sign_beta, sign_w2, sign_b2,
        dig_g, dig_beta, dig_w2, dig_b2,
        aux_w2, aux_b2, out);
}